// round 16
// baseline (speedup 1.0000x reference)
#include <cuda_runtime.h>
#include <cuda_fp16.h>
#include <cstdint>
#include <math.h>

// Problem constants
#define BB 131072
#define DD 64
#define dd 32
#define HH 512
#define NLAYER 3
#define NBLK 8
#define EPS 1e-5f

// ---------------------------------------------------------------------------
// asm helpers (sm_80-era instructions only: valid at compute_103 target)
// ---------------------------------------------------------------------------
__device__ __forceinline__ uint32_t smem_u32(const void* p) {
    uint32_t a;
    asm("{ .reg .u64 t; cvta.to.shared.u64 t, %1; cvt.u32.u64 %0, t; }" : "=r"(a) : "l"(p));
    return a;
}
#define CP16(S, G) \
    asm volatile("cp.async.cg.shared.global [%0], [%1], 16;" :: "r"(S), "l"(G))
#define CP_COMMIT() asm volatile("cp.async.commit_group;" ::: "memory")
#define CP_WAIT0()  asm volatile("cp.async.wait_group 0;" ::: "memory")

#define LDSM2(R, ADDR) \
    asm volatile("ldmatrix.sync.aligned.m8n8.x2.shared.b16 {%0,%1}, [%2];" \
        : "=r"((R)[0]), "=r"((R)[1]) : "r"(ADDR))

#define LDS128(R, ADDR) \
    asm volatile("ld.shared.v4.b32 {%0,%1,%2,%3}, [%4];" \
        : "=r"((R)[0]), "=r"((R)[1]), "=r"((R)[2]), "=r"((R)[3]) : "r"(ADDR))

#define MMA_FP16(D, A, B0, B1) \
    asm volatile("mma.sync.aligned.m16n8k16.row.col.f32.f16.f16.f32 " \
        "{%0,%1,%2,%3}, {%4,%5,%6,%7}, {%8,%9}, {%0,%1,%2,%3};" \
        : "+f"((D)[0]), "+f"((D)[1]), "+f"((D)[2]), "+f"((D)[3]) \
        : "r"((A)[0]), "r"((A)[1]), "r"((A)[2]), "r"((A)[3]), "r"(B0), "r"(B1))

// ---------------------------------------------------------------------------
// scratch (static device globals; no allocation)
// Activations in m16n8k16 A-fragment layout:
//   blob[((mtile*KT + ktile)*32 + lane)] = uint4 {a0,a1,a2,a3}
// Separate ping/pong per network chain (s and t run batched via grid.z).
// ---------------------------------------------------------------------------
__device__ uint4 g_as1[(size_t)(BB / 16) * 32 * 32];
__device__ uint4 g_as2[(size_t)(BB / 16) * 32 * 32];
__device__ uint4 g_at1[(size_t)(BB / 16) * 32 * 32];
__device__ uint4 g_at2[(size_t)(BB / 16) * 32 * 32];
__device__ uint4 g_y0[(size_t)(BB / 16) * 2 * 32];    // layer-0 input (K=32)
__device__ float g_yb[(size_t)BB * DD];
__device__ float g_zb[(size_t)BB * DD];
__device__ float g_sb[(size_t)BB * dd];
__device__ float g_tb[(size_t)BB * dd];
__device__ float g_logdet[BB];
__device__ double g_csum[DD];
__device__ double g_csumsq[DD];
__device__ float g_scale[DD];
__device__ float g_shift[DD];
__device__ float g_scalar;

// weight blobs: [N][K] fp16, hi and lo splits
#define HBLK_E   262144UL
#define HIDTOT_E (48UL * HBLK_E)
#define L0BLK_E  16384UL
#define L0TOT_E  (16UL * L0BLK_E)
#define OBLK_E   16384UL
#define WTOT_E   (HIDTOT_E + L0TOT_E + 16UL * OBLK_E)
__device__ __half g_whi[WTOT_E];
__device__ __half g_wlo[WTOT_E];

// ---------------------------------------------------------------------------
// helpers
// ---------------------------------------------------------------------------
__device__ __forceinline__ uint32_t pack2h(float a, float b) {
    __half2 h = __floats2half2_rn(a, b);
    return *(uint32_t*)&h;
}
__device__ __forceinline__ float fast_tanh(float x) {
    float e = __expf(2.0f * x);
    return 1.0f - __fdividef(2.0f, e + 1.0f);
}
__device__ __forceinline__ size_t frag_u32_idx(int r, int c, int KT) {
    int mt = r >> 4, kt = c >> 4;
    int lane = (r & 7) * 4 + ((c & 7) >> 1);
    int reg = ((r >> 3) & 1) + (((c >> 3) & 1) << 1);
    return ((size_t)(mt * KT + kt) * 32 + lane) * 4 + reg;
}
__device__ __forceinline__ void prep8h(const float* W, int Kdim, int Ndim,
                                       __half* dh, __half* dl, int t) {
    int n = t % Ndim;
    int k0 = (t / Ndim) * 8;
    ushort hs[8], ls[8];
#pragma unroll
    for (int j = 0; j < 8; ++j) {
        float w = W[(size_t)(k0 + j) * Ndim + n];
        __half h = __float2half_rn(w);
        __half l = __float2half_rn(w - __half2float(h));
        hs[j] = __half_as_ushort(h);
        ls[j] = __half_as_ushort(l);
    }
    *(uint4*)(dh + (size_t)n * Kdim + k0) = *(uint4*)hs;
    *(uint4*)(dl + (size_t)n * Kdim + k0) = *(uint4*)ls;
}

// ---------------------------------------------------------------------------
// single prep kernel: weights + y0-frag + init   (grid (128,1,97), block 256)
// ---------------------------------------------------------------------------
__global__ void k_prep_all(const float* __restrict__ sWh, const float* __restrict__ tWh,
                           const float* __restrict__ sW0, const float* __restrict__ tW0,
                           const float* __restrict__ sWo, const float* __restrict__ tWo,
                           const float* __restrict__ y) {
    const int z = blockIdx.z;
    const int t = blockIdx.x * 256 + threadIdx.x;
    if (z < 48) {
        int b = z / 6, r = z % 6;
        const float* W = (r < 3) ? sWh + (size_t)(b * 3 + r) * HH * HH
                                 : tWh + (size_t)(b * 3 + (r - 3)) * HH * HH;
        prep8h(W, HH, HH, g_whi + (size_t)z * HBLK_E, g_wlo + (size_t)z * HBLK_E, t);
    } else if (z < 64) {
        if (t >= 2048) return;
        int zz = z - 48, b = zz >> 1, m = zz & 1;
        const float* W = (m ? tW0 : sW0) + (size_t)b * dd * HH;   // [32][512]
        prep8h(W, dd, HH, g_whi + HIDTOT_E + (size_t)zz * L0BLK_E,
               g_wlo + HIDTOT_E + (size_t)zz * L0BLK_E, t);
    } else if (z < 80) {
        if (t >= 2048) return;
        int zz = z - 64, b = zz >> 1, m = zz & 1;
        const float* W = (m ? tWo : sWo) + (size_t)b * HH * dd;   // [512][32]
        prep8h(W, HH, dd, g_whi + HIDTOT_E + L0TOT_E + (size_t)zz * OBLK_E,
               g_wlo + HIDTOT_E + L0TOT_E + (size_t)zz * OBLK_E, t);
    } else if (z < 96) {
        // y0 (block 0 s-half = cols 0..31): fp16 fragment scatter
        int idx = (z - 80) * 32768 + t;     // 0..524287
        int r = idx >> 2;
        int c8 = (idx & 3) << 3;
        float f[8];
        *(float4*)&f[0] = *(const float4*)(y + (size_t)r * DD + c8);
        *(float4*)&f[4] = *(const float4*)(y + (size_t)r * DD + c8 + 4);
        uint32_t* blob = (uint32_t*)g_y0;
#pragma unroll
        for (int q = 0; q < 4; ++q) {
            int c = c8 + 2 * q;
            blob[frag_u32_idx(r, c, 2)] = pack2h(f[2 * q], f[2 * q + 1]);
        }
    } else {
        int i4 = t * 4;
        if (i4 < BB) *(float4*)(g_logdet + i4) = make_float4(0.f, 0.f, 0.f, 0.f);
        if (t < DD) { g_csum[t] = 0.0; g_csumsq[t] = 0.0; }
        if (t == 0) g_scalar = 0.0f;
    }
}

// ---------------------------------------------------------------------------
// HMMA GEMM, s/t batched via blockIdx.z. fp16: A single, W hi/lo x2.
// Warp tile 32x32 (MT=2, NT=4) -> acc 32 regs -> 3 CTAs/SM (24 warps).
// OUTMODE=0: fp32 row-major C, no act. OUTMODE=1: fp16-frag C, act z?relu:tanh.
// hidden/l0: BM=64, BN=128, 256 thr (warps 2Mx4N).  out: BM=128, BN=32, 128 thr.
// ---------------------------------------------------------------------------
template <int BM, int BN, int NK, int OUTMODE>
__global__ void __launch_bounds__((BN == 32) ? 128 : 256, 3) k_mma(
    const uint4* __restrict__ A0, const uint4* __restrict__ A1,
    const __half* __restrict__ Bh0, const __half* __restrict__ Bl0,
    const __half* __restrict__ Bh1, const __half* __restrict__ Bl1,
    const float* __restrict__ bias0, const float* __restrict__ bias1,
    uint4* __restrict__ C0, uint4* __restrict__ C1,
    float* __restrict__ Cf0, float* __restrict__ Cf1, int ldc)
{
    constexpr int THREADS = (BN == 32) ? 128 : 256;
    constexpr int K  = NK * 32;
    constexpr int KT = NK * 2;
    constexpr int MT = 2;
    constexpr int NT = 4;
    constexpr uint32_t AST4 = BM * 64;      // A stage bytes: (BM/16)*2*32*16
    constexpr uint32_t BST = BN * 80;
    constexpr uint32_t SS  = AST4 + 2 * BST;
    constexpr int T_TOT = BM * 4 + BN * 8;

    extern __shared__ unsigned char smraw[];
    const uint32_t sb = smem_u32(smraw);
    const int tid = threadIdx.x;
    const int wid = tid >> 5;
    const int L = tid & 31;
    const int z = blockIdx.z;
    const int bn = blockIdx.x * BN;
    const int wm = (BN == 32) ? wid * 32 : (wid >> 2) * 32;
    const int wn = (BN == 32) ? 0 : (wid & 3) * 32;
    const int mtw = wm >> 4;
    const int mtb_cta = blockIdx.y * (BM / 16);

    const uint4* Af = z ? A1 : A0;
    const __half* Bhi = z ? Bh1 : Bh0;
    const __half* Blo = z ? Bl1 : Bl0;
    const float* bias = z ? bias1 : bias0;

    float acc[MT][NT][4];
#pragma unroll
    for (int i = 0; i < MT; ++i)
#pragma unroll
        for (int j = 0; j < NT; ++j)
#pragma unroll
            for (int q = 0; q < 4; ++q) acc[i][j][q] = 0.0f;

    const uint32_t b_base = (uint32_t)(wn + (L & 7)) * 80u + (uint32_t)(((L >> 3) & 1) << 4);

    auto load_stage = [&](int st, int kc) {
        const uint32_t s0 = sb + (uint32_t)st * SS;
        const size_t kb = (size_t)kc * 32;
#pragma unroll
        for (int q = tid; q < T_TOT; q += THREADS) {
            if (q < BM * 4) {
                int f = q >> 5, lane = q & 31;
                int mtl = f >> 1, ktl = f & 1;
                CP16(s0 + (uint32_t)q * 16u,
                     Af + ((size_t)(mtb_cta + mtl) * KT + (2 * kc + ktl)) * 32 + lane);
            } else if (q < BM * 4 + BN * 4) {
                int p = q - BM * 4; int r = p >> 2, c = p & 3;
                CP16(s0 + AST4 + (uint32_t)r * 80u + (uint32_t)c * 16u,
                     Bhi + (size_t)(bn + r) * K + kb + c * 8);
            } else {
                int p = q - BM * 4 - BN * 4; int r = p >> 2, c = p & 3;
                CP16(s0 + AST4 + BST + (uint32_t)r * 80u + (uint32_t)c * 16u,
                     Blo + (size_t)(bn + r) * K + kb + c * 8);
            }
        }
    };

    load_stage(0, 0);
    CP_COMMIT();

    for (int kc = 0; kc < NK; ++kc) {
        CP_WAIT0();
        __syncthreads();
        if (kc + 1 < NK) load_stage((kc + 1) & 1, kc + 1);
        CP_COMMIT();
        const uint32_t s0 = sb + (uint32_t)(kc & 1) * SS;

#pragma unroll
        for (int ks = 0; ks < 2; ++ks) {
            uint32_t Afr[MT][4];
#pragma unroll
            for (int i = 0; i < MT; ++i)
                LDS128(Afr[i], s0 + (uint32_t)((((mtw + i) * 2 + ks) * 32 + L) * 16));

            uint32_t Bh[NT][2];
#pragma unroll
            for (int j = 0; j < NT; ++j)
                LDSM2(Bh[j], s0 + AST4 + b_base + j * 640u + ks * 32u);
#pragma unroll
            for (int i = 0; i < MT; ++i)
#pragma unroll
                for (int j = 0; j < NT; ++j)
                    MMA_FP16(acc[i][j], Afr[i], Bh[j][0], Bh[j][1]);

            uint32_t Bl[NT][2];
#pragma unroll
            for (int j = 0; j < NT; ++j)
                LDSM2(Bl[j], s0 + AST4 + BST + b_base + j * 640u + ks * 32u);
#pragma unroll
            for (int i = 0; i < MT; ++i)
#pragma unroll
                for (int j = 0; j < NT; ++j)
                    MMA_FP16(acc[i][j], Afr[i], Bl[j][0], Bl[j][1]);
        }
    }

    // epilogue
    if (OUTMODE == 0) {
        float* Cf = z ? Cf1 : Cf0;
#pragma unroll
        for (int i = 0; i < MT; ++i) {
            const size_t r0 = (size_t)blockIdx.y * BM + wm + i * 16 + (L >> 2);
            const size_t r1 = r0 + 8;
#pragma unroll
            for (int j = 0; j < NT; ++j) {
                const int n = bn + wn + j * 8 + ((L & 3) << 1);
                const float2 bs = *(const float2*)(bias + n);
                *(float2*)(Cf + r0 * ldc + n) = make_float2(acc[i][j][0] + bs.x, acc[i][j][1] + bs.y);
                *(float2*)(Cf + r1 * ldc + n) = make_float2(acc[i][j][2] + bs.x, acc[i][j][3] + bs.y);
            }
        }
    } else {
        uint4* Cfrag = z ? C1 : C0;
        const bool use_tanh = (z == 0);
#pragma unroll
        for (int i = 0; i < MT; ++i) {
            const int mt_g = mtb_cta + mtw + i;
#pragma unroll
            for (int t = 0; t < NT / 2; ++t) {
                const int kt_g = ((bn + wn) >> 4) + t;
                float v[8];
#pragma unroll
                for (int jj = 0; jj < 2; ++jj) {
                    const int j = 2 * t + jj;
                    const int n = bn + wn + j * 8 + ((L & 3) << 1);
                    const float2 bs = *(const float2*)(bias + n);
                    v[jj * 4 + 0] = acc[i][j][0] + bs.x;
                    v[jj * 4 + 1] = acc[i][j][1] + bs.y;
                    v[jj * 4 + 2] = acc[i][j][2] + bs.x;
                    v[jj * 4 + 3] = acc[i][j][3] + bs.y;
                }
#pragma unroll
                for (int q = 0; q < 8; ++q)
                    v[q] = use_tanh ? fast_tanh(v[q]) : fmaxf(v[q], 0.0f);
                uint4 u;
                u.x = pack2h(v[0], v[1]);
                u.y = pack2h(v[2], v[3]);
                u.z = pack2h(v[4], v[5]);
                u.w = pack2h(v[6], v[7]);
                Cfrag[((size_t)mt_g * 32 + kt_g) * 32 + L] = u;
            }
        }
    }
}

// ---------------------------------------------------------------------------
// small kernels
// ---------------------------------------------------------------------------
__global__ void k_bnapply(int sOff) {
    int idx = blockIdx.x * blockDim.x + threadIdx.x;   // BB*32 pair-slots
    int r = idx >> 5;
    int c0 = (idx & 31) << 1;
    float2 zv = *(const float2*)(g_zb + (size_t)r * DD + c0);
    float v0 = zv.x * g_scale[c0] + g_shift[c0];
    float v1 = zv.y * g_scale[c0 + 1] + g_shift[c0 + 1];
    *(float2*)(g_yb + (size_t)r * DD + c0) = make_float2(v0, v1);
    int cc = c0 - sOff;
    if ((unsigned)cc < 32u) {
        ((uint32_t*)g_y0)[frag_u32_idx(r, cc, 2)] = pack2h(v0, v1);
    }
}
__global__ void k_couple(const float* __restrict__ ysrc, int sOff) {
    int gt = blockIdx.x * blockDim.x + threadIdx.x;
    int row = gt >> 5;
    int j = gt & 31;
    if (row >= BB) return;
    int cOff = dd - sOff;
    float sv = g_sb[(size_t)row * dd + j];
    float tv = g_tb[(size_t)row * dd + j];
    float ys = ysrc[(size_t)row * DD + sOff + j];
    float yc = ysrc[(size_t)row * DD + cOff + j];
    float zc = yc * expf(sv) + tv;
    g_zb[(size_t)row * DD + sOff + j] = ys;
    g_zb[(size_t)row * DD + cOff + j] = zc;
    float sum = sv;
#pragma unroll
    for (int o = 16; o > 0; o >>= 1) sum += __shfl_xor_sync(0xffffffffu, sum, o);
    if (j == 0) g_logdet[row] += sum;
}
__global__ void k_colstats() {
    int c = threadIdx.x;
    int r = threadIdx.y;
    int start = blockIdx.x * 1024;
    float s = 0.0f, q = 0.0f;
    for (int i = start + r; i < start + 1024; i += 8) {
        float v = g_zb[(size_t)i * DD + c];
        s += v; q += v * v;
    }
    __shared__ float shs[8][64];
    __shared__ float shq[8][64];
    shs[r][c] = s; shq[r][c] = q;
    __syncthreads();
    if (r == 0) {
        double S = 0.0, Q = 0.0;
#pragma unroll
        for (int k = 0; k < 8; ++k) { S += (double)shs[k][c]; Q += (double)shq[k][c]; }
        atomicAdd(&g_csum[c], S);
        atomicAdd(&g_csumsq[c], Q);
    }
}
__global__ void k_finalize(const float* __restrict__ lg, const float* __restrict__ bt, int b) {
    int c = threadIdx.x;
    double mean = g_csum[c] / (double)BB;
    double var = (g_csumsq[c] - (double)BB * mean * mean) / (double)(BB - 1);
    double vpe = var + (double)EPS;
    float invstd = (float)(1.0 / sqrt(vpe));
    float lgc = lg[b * DD + c];
    float sc = expf(lgc) * invstd;
    g_scale[c] = sc;
    g_shift[c] = bt[b * DD + c] - (float)mean * sc;
    float term = lgc - 0.5f * (float)log(vpe);
    g_csum[c] = 0.0;
    g_csumsq[c] = 0.0;
    __shared__ float red[64];
    red[c] = term;
    __syncthreads();
    for (int o = 32; o > 0; o >>= 1) {
        if (c < o) red[c] += red[c + o];
        __syncthreads();
    }
    if (c == 0) g_scalar += red[0];
}
__global__ void k_output(float* __restrict__ out) {
    int idx = blockIdx.x * blockDim.x + threadIdx.x;
    if (idx < BB * DD) {
        int c = idx & (DD - 1);
        out[idx] = g_zb[idx] * g_scale[c] + g_shift[c];
    } else if (idx < BB * DD + BB) {
        int i = idx - BB * DD;
        out[(size_t)BB * DD + i] = g_logdet[i] + g_scalar;
    }
}

// ---------------------------------------------------------------------------
// launcher
// ---------------------------------------------------------------------------
extern "C" void kernel_launch(void* const* d_in, const int* in_sizes, int n_in,
                              void* d_out, int out_size) {
    (void)in_sizes; (void)n_in; (void)out_size;
    const float* y   = (const float*)d_in[0];
    const float* sW0 = (const float*)d_in[1];
    const float* sb0 = (const float*)d_in[2];
    const float* sWh = (const float*)d_in[3];
    const float* sbh = (const float*)d_in[4];
    const float* sWo = (const float*)d_in[5];
    const float* sbo = (const float*)d_in[6];
    const float* tW0 = (const float*)d_in[7];
    const float* tb0 = (const float*)d_in[8];
    const float* tWh = (const float*)d_in[9];
    const float* tbh = (const float*)d_in[10];
    const float* tWo = (const float*)d_in[11];
    const float* tbo = (const float*)d_in[12];
    const float* lg  = (const float*)d_in[13];
    const float* bt  = (const float*)d_in[14];
    float* out = (float*)d_out;

    uint4 *as1, *as2, *at1, *at2, *y0;
    __half *whi, *wlo;
    float *yb, *sbuf, *tbuf;
    cudaGetSymbolAddress((void**)&as1, g_as1);
    cudaGetSymbolAddress((void**)&as2, g_as2);
    cudaGetSymbolAddress((void**)&at1, g_at1);
    cudaGetSymbolAddress((void**)&at2, g_at2);
    cudaGetSymbolAddress((void**)&y0, g_y0);
    cudaGetSymbolAddress((void**)&whi, g_whi);
    cudaGetSymbolAddress((void**)&wlo, g_wlo);
    cudaGetSymbolAddress((void**)&yb, g_yb);
    cudaGetSymbolAddress((void**)&sbuf, g_sb);
    cudaGetSymbolAddress((void**)&tbuf, g_tb);

    // smem: hidden/l0: 2 x (4096 + 20480) = 49152 (3 CTA/SM = 147KB)
    //       out:       2 x (8192 + 5120)  = 26624
    const int SM_H = 2 * (64 * 64 + 2 * 128 * 80);
    const int SM_O = 2 * (128 * 64 + 2 * 32 * 80);
    cudaFuncSetAttribute(k_mma<64, 128, 16, 1>, cudaFuncAttributeMaxDynamicSharedMemorySize, SM_H);
    cudaFuncSetAttribute(k_mma<64, 128, 1, 1>,  cudaFuncAttributeMaxDynamicSharedMemorySize, SM_H);
    cudaFuncSetAttribute(k_mma<128, 32, 16, 0>, cudaFuncAttributeMaxDynamicSharedMemorySize, SM_O);

    // single prep launch so ncu (-s 5 -c 1) lands on a hidden k_mma
    { dim3 gp(128, 1, 97); k_prep_all<<<gp, 256>>>(sWh, tWh, sW0, tW0, sWo, tWo, y); }

    const dim3 GH(HH / 128, BB / 64, 2);  // (4, 2048, 2)
    const dim3 GO(1, BB / 128, 2);        // (1, 1024, 2)

    for (int b = 0; b < NBLK; ++b) {
        const float* ysrc = (b == 0) ? y : yb;
        const int sOff = (b & 1) ? dd : 0;
        if (b > 0) k_bnapply<<<(BB * 32) / 256, 256>>>(sOff);

        const __half* l0s_h = whi + HIDTOT_E + (size_t)(b * 2 + 0) * L0BLK_E;
        const __half* l0s_l = wlo + HIDTOT_E + (size_t)(b * 2 + 0) * L0BLK_E;
        const __half* l0t_h = whi + HIDTOT_E + (size_t)(b * 2 + 1) * L0BLK_E;
        const __half* l0t_l = wlo + HIDTOT_E + (size_t)(b * 2 + 1) * L0BLK_E;
        const __half* ots_h = whi + HIDTOT_E + L0TOT_E + (size_t)(b * 2 + 0) * OBLK_E;
        const __half* ots_l = wlo + HIDTOT_E + L0TOT_E + (size_t)(b * 2 + 0) * OBLK_E;
        const __half* ott_h = whi + HIDTOT_E + L0TOT_E + (size_t)(b * 2 + 1) * OBLK_E;
        const __half* ott_l = wlo + HIDTOT_E + L0TOT_E + (size_t)(b * 2 + 1) * OBLK_E;

        // layer 0 (s & t batched; same A = y0)
        k_mma<64, 128, 1, 1><<<GH, 256, SM_H>>>(
            y0, y0, l0s_h, l0s_l, l0t_h, l0t_l,
            sb0 + (size_t)b * HH, tb0 + (size_t)b * HH,
            as1, at1, nullptr, nullptr, 0);

        uint4 *cs = as1, *ns = as2, *ct = at1, *ntp = at2;
        for (int l = 0; l < NLAYER; ++l) {
            const size_t hos = (size_t)(b * 6 + l) * HBLK_E;
            const size_t hot = (size_t)(b * 6 + 3 + l) * HBLK_E;
            k_mma<64, 128, 16, 1><<<GH, 256, SM_H>>>(
                cs, ct, whi + hos, wlo + hos, whi + hot, wlo + hot,
                sbh + (size_t)(b * 3 + l) * HH, tbh + (size_t)(b * 3 + l) * HH,
                ns, ntp, nullptr, nullptr, 0);
            uint4* tp;
            tp = cs; cs = ns; ns = tp;
            tp = ct; ct = ntp; ntp = tp;
        }

        // out layers (s & t batched) -> fp32 sbuf/tbuf
        k_mma<128, 32, 16, 0><<<GO, 128, SM_O>>>(
            cs, ct, ots_h, ots_l, ott_h, ott_l,
            sbo + (size_t)b * dd, tbo + (size_t)b * dd,
            nullptr, nullptr, sbuf, tbuf, dd);

        // coupling + stats
        k_couple<<<(BB * 32 + 255) / 256, 256>>>(ysrc, sOff);
        k_colstats<<<128, dim3(64, 8)>>>();
        k_finalize<<<1, 64>>>(lg, bt, b);
    }

    k_output<<<(BB * DD + BB + 255) / 256, 256>>>(out);
}

// round 17
// speedup vs baseline: 1.8971x; 1.8971x over previous
#include <cuda_runtime.h>
#include <cuda_fp16.h>
#include <cstdint>
#include <math.h>

// Problem constants
#define BB 131072
#define DD 64
#define dd 32
#define HH 512
#define NLAYER 3
#define NBLK 8
#define EPS 1e-5f

// ---------------------------------------------------------------------------
// asm helpers (sm_80-era instructions only: valid at compute_103 target)
// ---------------------------------------------------------------------------
__device__ __forceinline__ uint32_t smem_u32(const void* p) {
    uint32_t a;
    asm("{ .reg .u64 t; cvta.to.shared.u64 t, %1; cvt.u32.u64 %0, t; }" : "=r"(a) : "l"(p));
    return a;
}
#define CP16(S, G) \
    asm volatile("cp.async.cg.shared.global [%0], [%1], 16;" :: "r"(S), "l"(G))
#define CP_COMMIT() asm volatile("cp.async.commit_group;" ::: "memory")
#define CP_WAIT0()  asm volatile("cp.async.wait_group 0;" ::: "memory")
#define CP_WAIT1()  asm volatile("cp.async.wait_group 1;" ::: "memory")

#define LDSM2(R, ADDR) \
    asm volatile("ldmatrix.sync.aligned.m8n8.x2.shared.b16 {%0,%1}, [%2];" \
        : "=r"((R)[0]), "=r"((R)[1]) : "r"(ADDR))

#define LDS128(R, ADDR) \
    asm volatile("ld.shared.v4.b32 {%0,%1,%2,%3}, [%4];" \
        : "=r"((R)[0]), "=r"((R)[1]), "=r"((R)[2]), "=r"((R)[3]) : "r"(ADDR))

#define MMA_FP16(D, A, B0, B1) \
    asm volatile("mma.sync.aligned.m16n8k16.row.col.f32.f16.f16.f32 " \
        "{%0,%1,%2,%3}, {%4,%5,%6,%7}, {%8,%9}, {%0,%1,%2,%3};" \
        : "+f"((D)[0]), "+f"((D)[1]), "+f"((D)[2]), "+f"((D)[3]) \
        : "r"((A)[0]), "r"((A)[1]), "r"((A)[2]), "r"((A)[3]), "r"(B0), "r"(B1))

// ---------------------------------------------------------------------------
// scratch (static device globals; no allocation)
// Activations live in m16n8k16 A-fragment layout:
//   blob[ ((mtile*KT + ktile)*32 + lane) ] = uint4 {a0,a1,a2,a3}
// ---------------------------------------------------------------------------
__device__ uint4 g_a1[(size_t)(BB / 16) * 32 * 32];   // hidden acts ping (128MB)
__device__ uint4 g_a2[(size_t)(BB / 16) * 32 * 32];   // hidden acts pong
__device__ uint4 g_y0[(size_t)(BB / 16) * 2 * 32];    // layer-0 input (K=32)
__device__ float g_yb[(size_t)BB * DD];
__device__ float g_zb[(size_t)BB * DD];
__device__ float g_sb[(size_t)BB * dd];
__device__ float g_tb[(size_t)BB * dd];
__device__ float g_logdet[BB];
__device__ double g_csum[DD];
__device__ double g_csumsq[DD];
__device__ float g_scale[DD];
__device__ float g_shift[DD];
__device__ float g_scalar;

// weight blobs: [N][K] fp16 (single rounding)
#define HBLK_E   262144UL
#define HIDTOT_E (48UL * HBLK_E)
#define L0BLK_E  16384UL
#define L0TOT_E  (16UL * L0BLK_E)
#define OBLK_E   16384UL
#define WTOT_E   (HIDTOT_E + L0TOT_E + 16UL * OBLK_E)
__device__ __half g_whi[WTOT_E];

// ---------------------------------------------------------------------------
// helpers
// ---------------------------------------------------------------------------
__device__ __forceinline__ uint32_t pack2h(float a, float b) {
    __half2 h = __floats2half2_rn(a, b);
    return *(uint32_t*)&h;
}
__device__ __forceinline__ float fast_tanh(float x) {
    float e = __expf(2.0f * x);
    return 1.0f - __fdividef(2.0f, e + 1.0f);
}
// fragment u32-slot for element pair (r, c),(r, c+1), c even; KT = K/16
__device__ __forceinline__ size_t frag_u32_idx(int r, int c, int KT) {
    int mt = r >> 4, kt = c >> 4;
    int lane = (r & 7) * 4 + ((c & 7) >> 1);
    int reg = ((r >> 3) & 1) + (((c >> 3) & 1) << 1);
    return ((size_t)(mt * KT + kt) * 32 + lane) * 4 + reg;
}
__device__ __forceinline__ void prep8h(const float* W, int Kdim, int Ndim,
                                       __half* dh, int t) {
    int n = t % Ndim;
    int k0 = (t / Ndim) * 8;
    ushort hs[8];
#pragma unroll
    for (int j = 0; j < 8; ++j) {
        float w = W[(size_t)(k0 + j) * Ndim + n];
        hs[j] = __half_as_ushort(__float2half_rn(w));
    }
    *(uint4*)(dh + (size_t)n * Kdim + k0) = *(uint4*)hs;
}

// ---------------------------------------------------------------------------
// single prep kernel: weights + y0-frag + init   (grid (128,1,97), block 256)
// ---------------------------------------------------------------------------
__global__ void k_prep_all(const float* __restrict__ sWh, const float* __restrict__ tWh,
                           const float* __restrict__ sW0, const float* __restrict__ tW0,
                           const float* __restrict__ sWo, const float* __restrict__ tWo,
                           const float* __restrict__ y) {
    const int z = blockIdx.z;
    const int t = blockIdx.x * 256 + threadIdx.x;
    if (z < 48) {
        int b = z / 6, r = z % 6;
        const float* W = (r < 3) ? sWh + (size_t)(b * 3 + r) * HH * HH
                                 : tWh + (size_t)(b * 3 + (r - 3)) * HH * HH;
        prep8h(W, HH, HH, g_whi + (size_t)z * HBLK_E, t);
    } else if (z < 64) {
        if (t >= 2048) return;
        int zz = z - 48, b = zz >> 1, m = zz & 1;
        const float* W = (m ? tW0 : sW0) + (size_t)b * dd * HH;   // [32][512]
        prep8h(W, dd, HH, g_whi + HIDTOT_E + (size_t)zz * L0BLK_E, t);
    } else if (z < 80) {
        if (t >= 2048) return;
        int zz = z - 64, b = zz >> 1, m = zz & 1;
        const float* W = (m ? tWo : sWo) + (size_t)b * HH * dd;   // [512][32]
        prep8h(W, HH, dd, g_whi + HIDTOT_E + L0TOT_E + (size_t)zz * OBLK_E, t);
    } else if (z < 96) {
        // y0 (block 0 s-half = cols 0..31): fp16 fragment scatter, 8 cols/thread
        int idx = (z - 80) * 32768 + t;     // 0..524287
        int r = idx >> 2;
        int c8 = (idx & 3) << 3;
        float f[8];
        *(float4*)&f[0] = *(const float4*)(y + (size_t)r * DD + c8);
        *(float4*)&f[4] = *(const float4*)(y + (size_t)r * DD + c8 + 4);
        uint32_t* blob = (uint32_t*)g_y0;
#pragma unroll
        for (int q = 0; q < 4; ++q) {
            int c = c8 + 2 * q;
            blob[frag_u32_idx(r, c, 2)] = pack2h(f[2 * q], f[2 * q + 1]);
        }
    } else {
        int i4 = t * 4;
        if (i4 < BB) *(float4*)(g_logdet + i4) = make_float4(0.f, 0.f, 0.f, 0.f);
        if (t < DD) { g_csum[t] = 0.0; g_csumsq[t] = 0.0; }
        if (t == 0) g_scalar = 0.0f;
    }
}

// ---------------------------------------------------------------------------
// HMMA GEMM: C[M,N] = act(A[M,K] @ W[K,N] + bias), single-product fp16.
// A staged via cp.async (raw fragment copy, 8KB/stage); B fp16 (80B rows).
// 3-stage pipeline (wait_group 1). BN=128: 8 warps, 64x32 tiles, 2 CTA/SM.
// ---------------------------------------------------------------------------
template <int BN, int NK, int ACT>
__global__ void __launch_bounds__((BN == 32) ? 128 : 256, 2) k_mma(
    const uint4* __restrict__ Af,
    const __half* __restrict__ Bhi,
    const float* __restrict__ bias,
    uint4* __restrict__ Cfrag,
    float* __restrict__ Cf, int ldc)
{
    constexpr int THREADS = (BN == 32) ? 128 : 256;
    constexpr int K  = NK * 32;
    constexpr int KT = NK * 2;          // K / 16
    constexpr int MT = (BN == 32) ? 2 : 4;
    constexpr int NT = 4;
    constexpr uint32_t AST4 = 8192;     // A stage: 16 fragments x 32 lanes x 16B
    constexpr uint32_t BST = BN * 80;
    constexpr uint32_t SS  = AST4 + BST;
    constexpr int T_TOT = 512 + BN * 4;
    constexpr int WAITN = (NK >= 2) ? 1 : 0;

    extern __shared__ unsigned char smraw[];
    const uint32_t sb = smem_u32(smraw);
    const int tid = threadIdx.x;
    const int wid = tid >> 5;
    const int L = tid & 31;
    const int bn = blockIdx.x * BN;
    const int wm = (BN == 32) ? wid * 32 : (wid >> 2) * 64;
    const int wn = (BN == 32) ? 0 : (wid & 3) * 32;
    const int mtw = (wm >> 4);          // warp's first m-tile (CTA-local)
    const int mtb_cta = blockIdx.y * 8; // CTA's first m-tile (global)

    float acc[MT][NT][4];
#pragma unroll
    for (int i = 0; i < MT; ++i)
#pragma unroll
        for (int j = 0; j < NT; ++j)
#pragma unroll
            for (int q = 0; q < 4; ++q) acc[i][j][q] = 0.0f;

    const uint32_t b_base = (uint32_t)(wn + (L & 7)) * 80u + (uint32_t)(((L >> 3) & 1) << 4);

    auto load_stage = [&](int st, int kc) {
        const uint32_t s0 = sb + (uint32_t)st * SS;
        const size_t kb = (size_t)kc * 32;
#pragma unroll
        for (int q = tid; q < T_TOT; q += THREADS) {
            if (q < 512) {
                // A fragment copy: frag f = (mt_local*2 + kt_local), lane = q&31
                int f = q >> 5, lane = q & 31;
                int mtl = f >> 1, ktl = f & 1;
                CP16(s0 + (uint32_t)q * 16u,
                     Af + ((size_t)(mtb_cta + mtl) * KT + (2 * kc + ktl)) * 32 + lane);
            } else {
                int p = q - 512; int r = p >> 2, c = p & 3;
                CP16(s0 + AST4 + (uint32_t)r * 80u + (uint32_t)c * 16u,
                     Bhi + (size_t)(bn + r) * K + kb + c * 8);
            }
        }
    };

    // prologue: 2 stages in flight
#pragma unroll
    for (int s = 0; s < 2; ++s) {
        if (s < NK) load_stage(s, s);
        CP_COMMIT();
    }

    for (int kc = 0; kc < NK; ++kc) {
        if constexpr (WAITN == 0) CP_WAIT0(); else CP_WAIT1();
        __syncthreads();
        if (kc + 2 < NK) load_stage((kc + 2) % 3, kc + 2);
        CP_COMMIT();
        const uint32_t s0 = sb + (uint32_t)(kc % 3) * SS;

#pragma unroll
        for (int ks = 0; ks < 2; ++ks) {
            uint32_t Afr[MT][4];
#pragma unroll
            for (int i = 0; i < MT; ++i)
                LDS128(Afr[i], s0 + (uint32_t)((((mtw + i) * 2 + ks) * 32 + L) * 16));

            uint32_t Bh[NT][2];
#pragma unroll
            for (int j = 0; j < NT; ++j)
                LDSM2(Bh[j], s0 + AST4 + b_base + j * 640u + ks * 32u);

            // same-acc MMAs are MT*NT apart (no RAW chains)
#pragma unroll
            for (int i = 0; i < MT; ++i)
#pragma unroll
                for (int j = 0; j < NT; ++j)
                    MMA_FP16(acc[i][j], Afr[i], Bh[j][0], Bh[j][1]);
        }
    }

    // epilogue
    if (ACT == 0) {
        // fp32 row-major (out layers; feeds k_couple)
#pragma unroll
        for (int i = 0; i < MT; ++i) {
            const size_t r0 = (size_t)blockIdx.y * 128 + wm + i * 16 + (L >> 2);
            const size_t r1 = r0 + 8;
#pragma unroll
            for (int j = 0; j < NT; ++j) {
                const int n = bn + wn + j * 8 + ((L & 3) << 1);
                const float2 bs = *(const float2*)(bias + n);
                *(float2*)(Cf + r0 * ldc + n) = make_float2(acc[i][j][0] + bs.x, acc[i][j][1] + bs.y);
                *(float2*)(Cf + r1 * ldc + n) = make_float2(acc[i][j][2] + bs.x, acc[i][j][3] + bs.y);
            }
        }
    } else {
        // fp16 fragment layout (next layer K = 512 -> KT_next = 32)
#pragma unroll
        for (int i = 0; i < MT; ++i) {
            const int mt_g = mtb_cta + mtw + i;
#pragma unroll
            for (int t = 0; t < NT / 2; ++t) {
                const int kt_g = ((bn + wn) >> 4) + t;
                float v[8];
#pragma unroll
                for (int jj = 0; jj < 2; ++jj) {
                    const int j = 2 * t + jj;
                    const int n = bn + wn + j * 8 + ((L & 3) << 1);
                    const float2 bs = *(const float2*)(bias + n);
                    v[jj * 4 + 0] = acc[i][j][0] + bs.x;
                    v[jj * 4 + 1] = acc[i][j][1] + bs.y;
                    v[jj * 4 + 2] = acc[i][j][2] + bs.x;
                    v[jj * 4 + 3] = acc[i][j][3] + bs.y;
                }
#pragma unroll
                for (int q = 0; q < 8; ++q) {
                    if (ACT == 1) v[q] = fast_tanh(v[q]);
                    else          v[q] = fmaxf(v[q], 0.0f);
                }
                uint4 u;
                u.x = pack2h(v[0], v[1]);
                u.y = pack2h(v[2], v[3]);
                u.z = pack2h(v[4], v[5]);
                u.w = pack2h(v[6], v[7]);
                Cfrag[((size_t)mt_g * 32 + kt_g) * 32 + L] = u;
            }
        }
    }
}

// ---------------------------------------------------------------------------
// small kernels
// ---------------------------------------------------------------------------
__global__ void k_bnapply(int sOff) {
    int idx = blockIdx.x * blockDim.x + threadIdx.x;   // BB*32 pair-slots
    int r = idx >> 5;
    int c0 = (idx & 31) << 1;
    float2 z = *(const float2*)(g_zb + (size_t)r * DD + c0);
    float v0 = z.x * g_scale[c0] + g_shift[c0];
    float v1 = z.y * g_scale[c0 + 1] + g_shift[c0 + 1];
    *(float2*)(g_yb + (size_t)r * DD + c0) = make_float2(v0, v1);
    int cc = c0 - sOff;
    if ((unsigned)cc < 32u) {
        ((uint32_t*)g_y0)[frag_u32_idx(r, cc, 2)] = pack2h(v0, v1);
    }
}
__global__ void k_couple(const float* __restrict__ ysrc, int sOff) {
    int gt = blockIdx.x * blockDim.x + threadIdx.x;
    int row = gt >> 5;
    int j = gt & 31;
    if (row >= BB) return;
    int cOff = dd - sOff;
    float sv = g_sb[(size_t)row * dd + j];
    float tv = g_tb[(size_t)row * dd + j];
    float ys = ysrc[(size_t)row * DD + sOff + j];
    float yc = ysrc[(size_t)row * DD + cOff + j];
    float zc = yc * expf(sv) + tv;
    g_zb[(size_t)row * DD + sOff + j] = ys;
    g_zb[(size_t)row * DD + cOff + j] = zc;
    float sum = sv;
#pragma unroll
    for (int o = 16; o > 0; o >>= 1) sum += __shfl_xor_sync(0xffffffffu, sum, o);
    if (j == 0) g_logdet[row] += sum;
}
__global__ void k_colstats() {
    int c = threadIdx.x;
    int r = threadIdx.y;
    int start = blockIdx.x * 1024;
    float s = 0.0f, q = 0.0f;
    for (int i = start + r; i < start + 1024; i += 8) {
        float v = g_zb[(size_t)i * DD + c];
        s += v; q += v * v;
    }
    __shared__ float shs[8][64];
    __shared__ float shq[8][64];
    shs[r][c] = s; shq[r][c] = q;
    __syncthreads();
    if (r == 0) {
        double S = 0.0, Q = 0.0;
#pragma unroll
        for (int k = 0; k < 8; ++k) { S += (double)shs[k][c]; Q += (double)shq[k][c]; }
        atomicAdd(&g_csum[c], S);
        atomicAdd(&g_csumsq[c], Q);
    }
}
__global__ void k_finalize(const float* __restrict__ lg, const float* __restrict__ bt, int b) {
    int c = threadIdx.x;
    double mean = g_csum[c] / (double)BB;
    double var = (g_csumsq[c] - (double)BB * mean * mean) / (double)(BB - 1);
    double vpe = var + (double)EPS;
    float invstd = (float)(1.0 / sqrt(vpe));
    float lgc = lg[b * DD + c];
    float sc = expf(lgc) * invstd;
    g_scale[c] = sc;
    g_shift[c] = bt[b * DD + c] - (float)mean * sc;
    float term = lgc - 0.5f * (float)log(vpe);
    g_csum[c] = 0.0;
    g_csumsq[c] = 0.0;
    __shared__ float red[64];
    red[c] = term;
    __syncthreads();
    for (int o = 32; o > 0; o >>= 1) {
        if (c < o) red[c] += red[c + o];
        __syncthreads();
    }
    if (c == 0) g_scalar += red[0];
}
__global__ void k_output(float* __restrict__ out) {
    int idx = blockIdx.x * blockDim.x + threadIdx.x;
    if (idx < BB * DD) {
        int c = idx & (DD - 1);
        out[idx] = g_zb[idx] * g_scale[c] + g_shift[c];
    } else if (idx < BB * DD + BB) {
        int i = idx - BB * DD;
        out[(size_t)BB * DD + i] = g_logdet[i] + g_scalar;
    }
}

// ---------------------------------------------------------------------------
// launcher
// ---------------------------------------------------------------------------
extern "C" void kernel_launch(void* const* d_in, const int* in_sizes, int n_in,
                              void* d_out, int out_size) {
    (void)in_sizes; (void)n_in; (void)out_size;
    const float* y   = (const float*)d_in[0];
    const float* sW0 = (const float*)d_in[1];
    const float* sb0 = (const float*)d_in[2];
    const float* sWh = (const float*)d_in[3];
    const float* sbh = (const float*)d_in[4];
    const float* sWo = (const float*)d_in[5];
    const float* sbo = (const float*)d_in[6];
    const float* tW0 = (const float*)d_in[7];
    const float* tb0 = (const float*)d_in[8];
    const float* tWh = (const float*)d_in[9];
    const float* tbh = (const float*)d_in[10];
    const float* tWo = (const float*)d_in[11];
    const float* tbo = (const float*)d_in[12];
    const float* lg  = (const float*)d_in[13];
    const float* bt  = (const float*)d_in[14];
    float* out = (float*)d_out;

    uint4 *a1, *a2, *y0;
    __half *whi;
    float *yb, *sbuf, *tbuf;
    cudaGetSymbolAddress((void**)&a1, g_a1);
    cudaGetSymbolAddress((void**)&a2, g_a2);
    cudaGetSymbolAddress((void**)&y0, g_y0);
    cudaGetSymbolAddress((void**)&whi, g_whi);
    cudaGetSymbolAddress((void**)&yb, g_yb);
    cudaGetSymbolAddress((void**)&sbuf, g_sb);
    cudaGetSymbolAddress((void**)&tbuf, g_tb);

    // smem: BN=128 -> 3 x (8192 + 10240) = 55296 (2 CTA/SM = 110KB < 228KB)
    //       BN=32  -> 3 x (8192 + 2560)  = 32256
    const int SM_H = 3 * (8192 + 128 * 80);
    const int SM_O = 3 * (8192 + 32 * 80);
    cudaFuncSetAttribute(k_mma<128, 16, 1>, cudaFuncAttributeMaxDynamicSharedMemorySize, SM_H);
    cudaFuncSetAttribute(k_mma<128, 16, 2>, cudaFuncAttributeMaxDynamicSharedMemorySize, SM_H);
    cudaFuncSetAttribute(k_mma<128, 1, 1>,  cudaFuncAttributeMaxDynamicSharedMemorySize, SM_H);
    cudaFuncSetAttribute(k_mma<128, 1, 2>,  cudaFuncAttributeMaxDynamicSharedMemorySize, SM_H);
    cudaFuncSetAttribute(k_mma<32, 16, 0>,  cudaFuncAttributeMaxDynamicSharedMemorySize, SM_O);

    // single prep launch so ncu (-s 5 -c 1) lands on a hidden k_mma
    { dim3 gp(128, 1, 97); k_prep_all<<<gp, 256>>>(sWh, tWh, sW0, tW0, sWo, tWo, y); }

    const dim3 GH(HH / 128, BB / 128);  // (4, 1024)
    const dim3 GO(1, BB / 128);         // (1, 1024)

    for (int b = 0; b < NBLK; ++b) {
        const float* ysrc = (b == 0) ? y : yb;
        const int sOff = (b & 1) ? dd : 0;
        if (b > 0) k_bnapply<<<(BB * 32) / 256, 256>>>(sOff);

        const __half* l0s = whi + HIDTOT_E + (size_t)(b * 2 + 0) * L0BLK_E;
        const __half* l0t = whi + HIDTOT_E + (size_t)(b * 2 + 1) * L0BLK_E;
        const __half* ots = whi + HIDTOT_E + L0TOT_E + (size_t)(b * 2 + 0) * OBLK_E;
        const __half* ott = whi + HIDTOT_E + L0TOT_E + (size_t)(b * 2 + 1) * OBLK_E;

        // ---- s MLP (tanh) ----
        k_mma<128, 1, 1><<<GH, 256, SM_H>>>(y0, l0s,
                                            sb0 + (size_t)b * HH, a1, nullptr, 0);
        uint4 *cur = a1, *nxt = a2;
        for (int l = 0; l < NLAYER; ++l) {
            const size_t ho = (size_t)(b * 6 + l) * HBLK_E;
            k_mma<128, 16, 1><<<GH, 256, SM_H>>>(cur, whi + ho,
                                                 sbh + (size_t)(b * 3 + l) * HH, nxt, nullptr, 0);
            uint4* tp = cur; cur = nxt; nxt = tp;
        }
        k_mma<32, 16, 0><<<GO, 128, SM_O>>>(cur, ots,
                                            sbo + (size_t)b * dd, nullptr, sbuf, dd);

        // ---- t MLP (relu) ----
        k_mma<128, 1, 2><<<GH, 256, SM_H>>>(y0, l0t,
                                            tb0 + (size_t)b * HH, a1, nullptr, 0);
        cur = a1; nxt = a2;
        for (int l = 0; l < NLAYER; ++l) {
            const size_t ho = (size_t)(b * 6 + 3 + l) * HBLK_E;
            k_mma<128, 16, 2><<<GH, 256, SM_H>>>(cur, whi + ho,
                                                 tbh + (size_t)(b * 3 + l) * HH, nxt, nullptr, 0);
            uint4* tp = cur; cur = nxt; nxt = tp;
        }
        k_mma<32, 16, 0><<<GO, 128, SM_O>>>(cur, ott,
                                            tbo + (size_t)b * dd, nullptr, tbuf, dd);

        // ---- coupling + stats ----
        k_couple<<<(BB * 32 + 255) / 256, 256>>>(ysrc, sOff);
        k_colstats<<<128, dim3(64, 8)>>>();
        k_finalize<<<1, 64>>>(lg, bt, b);
    }

    k_output<<<(BB * DD + BB + 255) / 256, 256>>>(out);
}